// round 2
// baseline (speedup 1.0000x reference)
#include <cuda_runtime.h>
#include <stdint.h>

// Problem dims (fixed by the dataset):
//   weights   [T=8]          fp32
//   bond_src  [B=1024,E=512] int32  (values 0..254, +1 applied)
//   bond_dst  [B=1024,E=512] int32
//   bond_type [B=1024,E=512] int32
//   num_nodes scalar (=256)
//   out       [B,256,256]    fp32  -> 256 MiB, HBM-write-bound
static constexpr int Bb    = 1024;
static constexpr int E     = 512;
static constexpr int Nn    = 256;
static constexpr int CELLS = Nn * Nn;       // 65536 floats per batch slice
static constexpr int TS    = 2048;          // hash slots (load factor <= 0.5)
static constexpr int THREADS = 512;

// Open-addressed smem hash. Entry: key(16b high) | prio(16b low). 0 == empty.
// key in [257, 65535] so a valid entry is never 0. prio in [1, 1024].
__device__ __forceinline__ void ht_insert(uint32_t* table, uint32_t key, uint32_t prio) {
    uint32_t entry = (key << 16) | prio;
    uint32_t h = (key * 2654435761u) >> (32 - 11);   // 11 bits -> [0, 2048)
    #pragma unroll 1
    while (true) {
        uint32_t cur = table[h];
        if (cur == 0u) {
            uint32_t old = atomicCAS(&table[h], 0u, entry);
            if (old == 0u) return;                   // claimed empty slot
            cur = old;                               // lost race; inspect winner
        }
        if ((cur >> 16) == key) {                    // same cell -> max priority wins
            atomicMax(&table[h], entry);             // high bits equal, so packed max == prio max
            return;
        }
        h = (h + 1) & (TS - 1);                      // linear probe
    }
}

__device__ __forceinline__ uint32_t ht_lookup(const uint32_t* table, uint32_t key) {
    uint32_t h = (key * 2654435761u) >> (32 - 11);
    #pragma unroll 1
    while (true) {
        uint32_t cur = table[h];
        if ((cur >> 16) == key) return cur & 0xFFFFu;
        h = (h + 1) & (TS - 1);
    }
}

__global__ __launch_bounds__(THREADS, 2)
void bond_weight_kernel(const float* __restrict__ weights,
                        const int*   __restrict__ bond_src,
                        const int*   __restrict__ bond_dst,
                        const int*   __restrict__ bond_type,
                        float*       __restrict__ out)
{
    __shared__ uint32_t table[TS];

    const int b = blockIdx.x;
    const int t = threadIdx.x;

    // ---- clear hash table (8 KB) ----
    #pragma unroll
    for (int i = 0; i < TS / THREADS; i++)
        table[t + i * THREADS] = 0u;

    // ---- load this thread's edge & start dedup inserts ----
    const int  eidx = b * E + t;            // 512 threads == 512 edges per batch
    const int  s = bond_src[eidx] + 1;      // 1..255
    const int  d = bond_dst[eidx] + 1;      // 1..255
    const float w = weights[bond_type[eidx]];

    const uint32_t key1 = (uint32_t)(s * Nn + d);   // pass 0: out[b, src, dst]
    const uint32_t key2 = (uint32_t)(d * Nn + s);   // pass 1: out[b, dst, src]
    const uint32_t prio1 = (uint32_t)(t + 1);       // sequential-application order:
    const uint32_t prio2 = (uint32_t)(E + t + 1);   // pass1 beats pass0; higher e wins

    // ---- zero this batch's 256 KB slice with float4 stores ----
    float4* o4 = reinterpret_cast<float4*>(out + (size_t)b * CELLS);
    const float4 z = make_float4(0.f, 0.f, 0.f, 0.f);
    #pragma unroll
    for (int i = 0; i < (CELLS / 4) / THREADS; i++)   // 16384 float4 / 512 thr = 32 each
        o4[t + i * THREADS] = z;

    __syncthreads();     // table cleared before inserts (zero-fill stores can still drain)

    ht_insert(table, key1, prio1);
    ht_insert(table, key2, prio2);

    __syncthreads();     // all inserts done; zero-fill complete before sparse overwrite

    // ---- emit only the winning write per cell (deterministic, race-free) ----
    float* o = out + (size_t)b * CELLS;
    if (ht_lookup(table, key1) == prio1) o[key1] = w;
    if (ht_lookup(table, key2) == prio2) o[key2] = w;
}

extern "C" void kernel_launch(void* const* d_in, const int* in_sizes, int n_in,
                              void* d_out, int out_size)
{
    const float* weights   = (const float*)d_in[0];
    const int*   bond_src  = (const int*)  d_in[1];
    const int*   bond_dst  = (const int*)  d_in[2];
    const int*   bond_type = (const int*)  d_in[3];
    // d_in[4] = num_nodes (compile-time 256 here)
    float* out = (float*)d_out;

    bond_weight_kernel<<<Bb, THREADS>>>(weights, bond_src, bond_dst, bond_type, out);
}

// round 3
// speedup vs baseline: 1.2591x; 1.2591x over previous
#include <cuda_runtime.h>
#include <stdint.h>

// weights[T=8] f32; bond_src/dst/type [B=1024,E=512] i32 (+1 node offset);
// out [B,256,256] f32 (256 MiB) -> pure HBM-write-bound.
// Strategy: one block per batch. Build smem hash (dedup, reference last-write-wins
// order) + smem bitmap of occupied cells + smem value table. Then write the whole
// 256KB slice in ONE coalesced streaming pass (each line written exactly once,
// no read-for-ownership, no L2 pollution).
static constexpr int Bb      = 1024;
static constexpr int E       = 512;
static constexpr int Nn      = 256;
static constexpr int CELLS   = Nn * Nn;     // 65536 cells / batch
static constexpr int TS      = 2048;        // hash slots (<=0.5 load)
static constexpr int THREADS = 512;

__device__ __forceinline__ uint32_t ht_hash(uint32_t key) {
    return (key * 2654435761u) >> (32 - 11);          // -> [0, 2048)
}

// Entry: key(16b hi) | prio(16b lo). key in [257,65535] so entry!=0 when valid.
__device__ __forceinline__ void ht_insert(uint32_t* table, uint32_t key, uint32_t prio) {
    uint32_t entry = (key << 16) | prio;
    uint32_t h = ht_hash(key);
    #pragma unroll 1
    while (true) {
        uint32_t cur = table[h];
        if (cur == 0u) {
            uint32_t old = atomicCAS(&table[h], 0u, entry);
            if (old == 0u) return;
            cur = old;
        }
        if ((cur >> 16) == key) {          // same cell: max prio wins (hi bits equal)
            atomicMax(&table[h], entry);
            return;
        }
        h = (h + 1) & (TS - 1);
    }
}

__device__ __forceinline__ uint32_t ht_find_slot(const uint32_t* table, uint32_t key) {
    uint32_t h = ht_hash(key);
    #pragma unroll 1
    while ((table[h] >> 16) != key) h = (h + 1) & (TS - 1);
    return h;
}

__global__ __launch_bounds__(THREADS, 4)
void bond_weight_kernel(const float* __restrict__ weights,
                        const int*   __restrict__ bond_src,
                        const int*   __restrict__ bond_dst,
                        const int*   __restrict__ bond_type,
                        float*       __restrict__ out)
{
    __shared__ uint32_t table[TS];     // key|prio
    __shared__ float    value[TS];     // winning weight per slot
    __shared__ uint32_t bitmap[CELLS / 32];   // 2048 words: occupied cells

    const int b = blockIdx.x;
    const int t = threadIdx.x;

    // ---- clear hash + bitmap ----
    #pragma unroll
    for (int i = 0; i < TS / THREADS; i++) {
        table [t + i * THREADS] = 0u;
        bitmap[t + i * THREADS] = 0u;
    }

    // ---- this thread's edge ----
    const int   eidx = b * E + t;                  // 512 threads == 512 edges
    const int   s = bond_src[eidx] + 1;            // 1..255
    const int   d = bond_dst[eidx] + 1;
    const float w = weights[bond_type[eidx]];

    const uint32_t key1  = (uint32_t)(s * Nn + d); // pass 0: [src,dst]
    const uint32_t key2  = (uint32_t)(d * Nn + s); // pass 1: [dst,src]
    const uint32_t prio1 = (uint32_t)(t + 1);      // ref applies pass0 e=0..E-1, then pass1
    const uint32_t prio2 = (uint32_t)(E + t + 1);  // later application wins

    __syncthreads();   // clears visible

    ht_insert(table, key1, prio1);
    ht_insert(table, key2, prio2);
    atomicOr(&bitmap[key1 >> 5], 1u << (key1 & 31));
    atomicOr(&bitmap[key2 >> 5], 1u << (key2 & 31));

    __syncthreads();   // inserts + bitmap done

    // ---- winners publish their weight ----
    {
        uint32_t s1 = ht_find_slot(table, key1);
        if ((table[s1] & 0xFFFFu) == prio1) value[s1] = w;
        uint32_t s2 = ht_find_slot(table, key2);
        if ((table[s2] & 0xFFFFu) == prio2) value[s2] = w;
    }

    __syncthreads();   // values ready

    // ---- single streaming pass over the 256KB slice ----
    float4* o4 = reinterpret_cast<float4*>(out + (size_t)b * CELLS);
    const float4 z = make_float4(0.f, 0.f, 0.f, 0.f);

    #pragma unroll
    for (int i = 0; i < (CELLS / 4) / THREADS; i++) {   // 32 float4 per thread
        const int idx = i * THREADS + t;                // float4 index in slice
        // 8 float4s per bitmap word; adjacent threads share a word (LDS broadcast)
        const uint32_t word = bitmap[idx >> 3];
        const uint32_t nib  = (word >> ((idx & 7) * 4)) & 0xFu;
        float4 v = z;
        if (nib) {                                      // rare (~1.5% of nibbles)
            const uint32_t c0 = (uint32_t)idx * 4u;
            if (nib & 1u) v.x = value[ht_find_slot(table, c0 + 0u)];
            if (nib & 2u) v.y = value[ht_find_slot(table, c0 + 1u)];
            if (nib & 4u) v.z = value[ht_find_slot(table, c0 + 2u)];
            if (nib & 8u) v.w = value[ht_find_slot(table, c0 + 3u)];
        }
        __stcs(o4 + idx, v);    // streaming: never re-read, keep out of L2
    }
}

extern "C" void kernel_launch(void* const* d_in, const int* in_sizes, int n_in,
                              void* d_out, int out_size)
{
    const float* weights   = (const float*)d_in[0];
    const int*   bond_src  = (const int*)  d_in[1];
    const int*   bond_dst  = (const int*)  d_in[2];
    const int*   bond_type = (const int*)  d_in[3];
    float* out = (float*)d_out;

    bond_weight_kernel<<<Bb, THREADS>>>(weights, bond_src, bond_dst, bond_type, out);
}

// round 4
// speedup vs baseline: 1.2624x; 1.0026x over previous
#include <cuda_runtime.h>
#include <stdint.h>

// weights[T=8] f32; bond_src/dst/type [B=1024,E=512] i32 (+1 node offset);
// out [B,256,256] f32 (256 MiB) -> pure HBM-write-bound.
// Strategy: one block per batch. Build smem hash (dedup, reference last-write-wins
// order) + smem bitmap of occupied cells + smem value table. Then write the whole
// 256KB slice in ONE coalesced streaming pass (each line written exactly once,
// no read-for-ownership, no L2 pollution).
static constexpr int Bb      = 1024;
static constexpr int E       = 512;
static constexpr int Nn      = 256;
static constexpr int CELLS   = Nn * Nn;     // 65536 cells / batch
static constexpr int TS      = 2048;        // hash slots (<=0.5 load)
static constexpr int THREADS = 512;

__device__ __forceinline__ uint32_t ht_hash(uint32_t key) {
    return (key * 2654435761u) >> (32 - 11);          // -> [0, 2048)
}

// Entry: key(16b hi) | prio(16b lo). key in [257,65535] so entry!=0 when valid.
__device__ __forceinline__ void ht_insert(uint32_t* table, uint32_t key, uint32_t prio) {
    uint32_t entry = (key << 16) | prio;
    uint32_t h = ht_hash(key);
    #pragma unroll 1
    while (true) {
        uint32_t cur = table[h];
        if (cur == 0u) {
            uint32_t old = atomicCAS(&table[h], 0u, entry);
            if (old == 0u) return;
            cur = old;
        }
        if ((cur >> 16) == key) {          // same cell: max prio wins (hi bits equal)
            atomicMax(&table[h], entry);
            return;
        }
        h = (h + 1) & (TS - 1);
    }
}

__device__ __forceinline__ uint32_t ht_find_slot(const uint32_t* table, uint32_t key) {
    uint32_t h = ht_hash(key);
    #pragma unroll 1
    while ((table[h] >> 16) != key) h = (h + 1) & (TS - 1);
    return h;
}

__global__ __launch_bounds__(THREADS, 4)
void bond_weight_kernel(const float* __restrict__ weights,
                        const int*   __restrict__ bond_src,
                        const int*   __restrict__ bond_dst,
                        const int*   __restrict__ bond_type,
                        float*       __restrict__ out)
{
    __shared__ uint32_t table[TS];     // key|prio
    __shared__ float    value[TS];     // winning weight per slot
    __shared__ uint32_t bitmap[CELLS / 32];   // 2048 words: occupied cells

    const int b = blockIdx.x;
    const int t = threadIdx.x;

    // ---- clear hash + bitmap ----
    #pragma unroll
    for (int i = 0; i < TS / THREADS; i++) {
        table [t + i * THREADS] = 0u;
        bitmap[t + i * THREADS] = 0u;
    }

    // ---- this thread's edge ----
    const int   eidx = b * E + t;                  // 512 threads == 512 edges
    const int   s = bond_src[eidx] + 1;            // 1..255
    const int   d = bond_dst[eidx] + 1;
    const float w = weights[bond_type[eidx]];

    const uint32_t key1  = (uint32_t)(s * Nn + d); // pass 0: [src,dst]
    const uint32_t key2  = (uint32_t)(d * Nn + s); // pass 1: [dst,src]
    const uint32_t prio1 = (uint32_t)(t + 1);      // ref applies pass0 e=0..E-1, then pass1
    const uint32_t prio2 = (uint32_t)(E + t + 1);  // later application wins

    __syncthreads();   // clears visible

    ht_insert(table, key1, prio1);
    ht_insert(table, key2, prio2);
    atomicOr(&bitmap[key1 >> 5], 1u << (key1 & 31));
    atomicOr(&bitmap[key2 >> 5], 1u << (key2 & 31));

    __syncthreads();   // inserts + bitmap done

    // ---- winners publish their weight ----
    {
        uint32_t s1 = ht_find_slot(table, key1);
        if ((table[s1] & 0xFFFFu) == prio1) value[s1] = w;
        uint32_t s2 = ht_find_slot(table, key2);
        if ((table[s2] & 0xFFFFu) == prio2) value[s2] = w;
    }

    __syncthreads();   // values ready

    // ---- single streaming pass over the 256KB slice ----
    float4* o4 = reinterpret_cast<float4*>(out + (size_t)b * CELLS);
    const float4 z = make_float4(0.f, 0.f, 0.f, 0.f);

    #pragma unroll
    for (int i = 0; i < (CELLS / 4) / THREADS; i++) {   // 32 float4 per thread
        const int idx = i * THREADS + t;                // float4 index in slice
        // 8 float4s per bitmap word; adjacent threads share a word (LDS broadcast)
        const uint32_t word = bitmap[idx >> 3];
        const uint32_t nib  = (word >> ((idx & 7) * 4)) & 0xFu;
        float4 v = z;
        if (nib) {                                      // rare (~1.5% of nibbles)
            const uint32_t c0 = (uint32_t)idx * 4u;
            if (nib & 1u) v.x = value[ht_find_slot(table, c0 + 0u)];
            if (nib & 2u) v.y = value[ht_find_slot(table, c0 + 1u)];
            if (nib & 4u) v.z = value[ht_find_slot(table, c0 + 2u)];
            if (nib & 8u) v.w = value[ht_find_slot(table, c0 + 3u)];
        }
        __stcs(o4 + idx, v);    // streaming: never re-read, keep out of L2
    }
}

extern "C" void kernel_launch(void* const* d_in, const int* in_sizes, int n_in,
                              void* d_out, int out_size)
{
    const float* weights   = (const float*)d_in[0];
    const int*   bond_src  = (const int*)  d_in[1];
    const int*   bond_dst  = (const int*)  d_in[2];
    const int*   bond_type = (const int*)  d_in[3];
    float* out = (float*)d_out;

    bond_weight_kernel<<<Bb, THREADS>>>(weights, bond_src, bond_dst, bond_type, out);
}

// round 5
// speedup vs baseline: 1.5057x; 1.1927x over previous
#include <cuda_runtime.h>
#include <stdint.h>

// weights[T=8] f32; bond_src/dst/type [B=1024,E=512] i32 (+1 node offset);
// out [B,256,256] f32 (256 MiB) -> HBM-write-bound target.
// One block per batch: smem hash for dedup (reference last-write-wins order),
// bitmap of occupied cells, rank (prefix popcounts) + compact value array so the
// streaming write loop resolves set cells in O(1) (no hash probing in hot loop).
static constexpr int Bb      = 1024;
static constexpr int E       = 512;
static constexpr int Nn      = 256;
static constexpr int CELLS   = Nn * Nn;     // 65536 cells / batch
static constexpr int NWORDS  = CELLS / 32;  // 2048 bitmap words
static constexpr int TS      = 2048;        // hash slots (<=0.5 load)
static constexpr int THREADS = 512;

__device__ __forceinline__ uint32_t ht_hash(uint32_t key) {
    return (key * 2654435761u) >> (32 - 11);          // -> [0, 2048)
}

// Entry: key(16b hi) | prio(16b lo). key in [257,65535] so entry!=0 when valid.
__device__ __forceinline__ void ht_insert(uint32_t* table, uint32_t key, uint32_t prio) {
    uint32_t entry = (key << 16) | prio;
    uint32_t h = ht_hash(key);
    #pragma unroll 1
    while (true) {
        uint32_t cur = table[h];
        if (cur == 0u) {
            uint32_t old = atomicCAS(&table[h], 0u, entry);
            if (old == 0u) return;
            cur = old;
        }
        if ((cur >> 16) == key) {          // same cell: max prio wins (hi bits equal)
            atomicMax(&table[h], entry);
            return;
        }
        h = (h + 1) & (TS - 1);
    }
}

__device__ __forceinline__ uint32_t ht_find_slot(const uint32_t* table, uint32_t key) {
    uint32_t h = ht_hash(key);
    #pragma unroll 1
    while ((table[h] >> 16) != key) h = (h + 1) & (TS - 1);
    return h;
}

__global__ __launch_bounds__(THREADS, 4)
void bond_weight_kernel(const float* __restrict__ weights,
                        const int*   __restrict__ bond_src,
                        const int*   __restrict__ bond_dst,
                        const int*   __restrict__ bond_type,
                        float*       __restrict__ out)
{
    __shared__ uint32_t table[TS];          // key|prio (8 KB)
    __shared__ uint32_t bitmap[NWORDS];     // occupied cells (8 KB)
    __shared__ uint16_t rankw[NWORDS];      // exclusive prefix popcount per word (4 KB)
    __shared__ float    cvals[2 * E];       // compact winner values, cell-id order (4 KB)
    __shared__ uint32_t warpsum[16];

    const int b = blockIdx.x;
    const int t = threadIdx.x;

    // ---- clear hash + bitmap ----
    #pragma unroll
    for (int i = 0; i < NWORDS / THREADS; i++) {
        table [t + i * THREADS] = 0u;
        bitmap[t + i * THREADS] = 0u;
    }

    // ---- this thread's edge ----
    const int   eidx = b * E + t;                  // 512 threads == 512 edges
    const int   s = bond_src[eidx] + 1;            // 1..255
    const int   d = bond_dst[eidx] + 1;
    const float w = weights[bond_type[eidx]];

    const uint32_t key1  = (uint32_t)(s * Nn + d); // pass 0: [src,dst]
    const uint32_t key2  = (uint32_t)(d * Nn + s); // pass 1: [dst,src]
    const uint32_t prio1 = (uint32_t)(t + 1);      // ref: pass0 e=0..E-1, then pass1;
    const uint32_t prio2 = (uint32_t)(E + t + 1);  // later application wins

    __syncthreads();   // clears visible

    ht_insert(table, key1, prio1);
    ht_insert(table, key2, prio2);
    atomicOr(&bitmap[key1 >> 5], 1u << (key1 & 31));
    atomicOr(&bitmap[key2 >> 5], 1u << (key2 & 31));

    __syncthreads();   // inserts + bitmap final

    // ---- block-wide exclusive prefix sum of per-word popcounts ----
    {
        const int base4 = t * 4;                   // 512 threads x 4 words = 2048
        const uint32_t c0 = __popc(bitmap[base4 + 0]);
        const uint32_t c1 = __popc(bitmap[base4 + 1]);
        const uint32_t c2 = __popc(bitmap[base4 + 2]);
        const uint32_t c3 = __popc(bitmap[base4 + 3]);
        const uint32_t ssum = c0 + c1 + c2 + c3;

        const uint32_t lane = t & 31, wrp = t >> 5;
        uint32_t x = ssum;
        #pragma unroll
        for (int off = 1; off < 32; off <<= 1) {
            uint32_t y = __shfl_up_sync(0xFFFFFFFFu, x, off);
            if (lane >= off) x += y;
        }
        if (lane == 31) warpsum[wrp] = x;          // warp totals (inclusive)
        __syncthreads();
        if (t == 0) {                              // serial scan of 16 warp totals
            uint32_t acc = 0;
            #pragma unroll
            for (int i = 0; i < 16; i++) { uint32_t v = warpsum[i]; warpsum[i] = acc; acc += v; }
        }
        __syncthreads();
        const uint32_t excl = warpsum[wrp] + (x - ssum);   // thread-exclusive prefix
        rankw[base4 + 0] = (uint16_t)(excl);
        rankw[base4 + 1] = (uint16_t)(excl + c0);
        rankw[base4 + 2] = (uint16_t)(excl + c0 + c1);
        rankw[base4 + 3] = (uint16_t)(excl + c0 + c1 + c2);
    }
    __syncthreads();   // rank ready

    // ---- winners deposit values at their compact (cell-id-ordered) position ----
    {
        uint32_t s1 = ht_find_slot(table, key1);
        if ((table[s1] & 0xFFFFu) == prio1) {
            uint32_t wd = key1 >> 5, bt = key1 & 31;
            uint32_t pos = (uint32_t)rankw[wd] + __popc(bitmap[wd] & ((1u << bt) - 1u));
            cvals[pos] = w;
        }
        uint32_t s2 = ht_find_slot(table, key2);
        if ((table[s2] & 0xFFFFu) == prio2) {
            uint32_t wd = key2 >> 5, bt = key2 & 31;
            uint32_t pos = (uint32_t)rankw[wd] + __popc(bitmap[wd] & ((1u << bt) - 1u));
            cvals[pos] = w;
        }
    }
    __syncthreads();   // cvals ready

    // ---- single streaming pass over the 256 KB slice (O(1) rare-path) ----
    float4* o4 = reinterpret_cast<float4*>(out + (size_t)b * CELLS);
    const float4 z = make_float4(0.f, 0.f, 0.f, 0.f);

    #pragma unroll
    for (int i = 0; i < (CELLS / 4) / THREADS; i++) {   // 32 float4 per thread
        const int idx = i * THREADS + t;                // coalesced float4 index
        const uint32_t word = bitmap[idx >> 3];         // 8 float4 per word (LDS bcast)
        const uint32_t sh   = (idx & 7) * 4;
        const uint32_t nib  = (word >> sh) & 0xFu;
        float4 v = z;
        if (nib) {                                      // ~6% of nibbles; O(1) now
            uint32_t p = (uint32_t)rankw[idx >> 3] + __popc(word & ((1u << sh) - 1u));
            if (nib & 1u) v.x = cvals[p++];
            if (nib & 2u) v.y = cvals[p++];
            if (nib & 4u) v.z = cvals[p++];
            if (nib & 8u) v.w = cvals[p];
        }
        __stcs(o4 + idx, v);    // streaming store: written once, never re-read
    }
}

extern "C" void kernel_launch(void* const* d_in, const int* in_sizes, int n_in,
                              void* d_out, int out_size)
{
    const float* weights   = (const float*)d_in[0];
    const int*   bond_src  = (const int*)  d_in[1];
    const int*   bond_dst  = (const int*)  d_in[2];
    const int*   bond_type = (const int*)  d_in[3];
    float* out = (float*)d_out;

    bond_weight_kernel<<<Bb, THREADS>>>(weights, bond_src, bond_dst, bond_type, out);
}